// round 1
// baseline (speedup 1.0000x reference)
#include <cuda_runtime.h>
#include <math.h>

#define B_ 8
#define P_ 100
#define N_ 50000
#define D_ 128
#define K_ 512

// Scratch (static device globals — no runtime allocation)
__device__ float g_fastsim[(size_t)B_ * P_ * N_];   // 160 MB
__device__ float g_posW[B_ * P_ * D_];              // 400 KB

// ---------------------------------------------------------------------------
// Kernel 0: posW[b,p,:] = pos[b,p,:] @ W   (W is [D,D] row-major, 'bpd,de->bpe')
// ---------------------------------------------------------------------------
__global__ void posw_kernel(const float* __restrict__ pos, const float* __restrict__ W) {
    int row = blockIdx.x;            // b*P + p
    int e = threadIdx.x;             // 0..127
    __shared__ float sp[D_];
    sp[e] = pos[(size_t)row * D_ + e];
    __syncthreads();
    float acc = 0.f;
#pragma unroll 8
    for (int d = 0; d < D_; ++d)
        acc = fmaf(sp[d], W[d * D_ + e], acc);
    g_posW[row * D_ + e] = acc;
}

// ---------------------------------------------------------------------------
// Kernel 1: fast_sim[b,p,n] = pos[b,p,:] . neg[b,n,:]
// Tiled SGEMM: 64(p) x 64(n) tile, 256 threads, 4x4 microtile, K staged in 2x64
// ---------------------------------------------------------------------------
#define TP 64
#define TN 64
#define KC 64

__global__ void __launch_bounds__(256) fastsim_kernel(const float* __restrict__ pos,
                                                      const float* __restrict__ neg) {
    __shared__ float As[KC][TP + 4];   // [k][p]
    __shared__ float Bs[KC][TN + 4];   // [k][n]

    int b  = blockIdx.z;
    int p0 = blockIdx.y * TP;
    int n0 = blockIdx.x * TN;
    int tid = threadIdx.x;
    int tx = tid & 15;        // n group
    int ty = tid >> 4;        // p group

    const float* Ab = pos + (size_t)b * P_ * D_;
    const float* Bb = neg + (size_t)b * N_ * D_;

    float acc[4][4];
#pragma unroll
    for (int i = 0; i < 4; ++i)
#pragma unroll
        for (int j = 0; j < 4; ++j) acc[i][j] = 0.f;

    for (int kc = 0; kc < D_; kc += KC) {
        // Load A and B tiles (64 rows x 64 k-cols each), transposed into smem.
#pragma unroll
        for (int i = 0; i < 4; ++i) {
            int f = i * 256 + tid;       // float4 index, 0..1023
            int r = f >> 4;              // row within tile, 0..63
            int c = (f & 15) << 2;       // k-col within chunk, 0..60

            float4 va = make_float4(0.f, 0.f, 0.f, 0.f);
            int p = p0 + r;
            if (p < P_) va = *(const float4*)(Ab + (size_t)p * D_ + kc + c);
            As[c + 0][r] = va.x; As[c + 1][r] = va.y;
            As[c + 2][r] = va.z; As[c + 3][r] = va.w;

            float4 vb = make_float4(0.f, 0.f, 0.f, 0.f);
            int n = n0 + r;
            if (n < N_) vb = *(const float4*)(Bb + (size_t)n * D_ + kc + c);
            Bs[c + 0][r] = vb.x; Bs[c + 1][r] = vb.y;
            Bs[c + 2][r] = vb.z; Bs[c + 3][r] = vb.w;
        }
        __syncthreads();

#pragma unroll
        for (int k = 0; k < KC; ++k) {
            float4 a  = *(const float4*)&As[k][ty << 2];
            float4 bb = *(const float4*)&Bs[k][tx << 2];
            acc[0][0] = fmaf(a.x, bb.x, acc[0][0]);
            acc[0][1] = fmaf(a.x, bb.y, acc[0][1]);
            acc[0][2] = fmaf(a.x, bb.z, acc[0][2]);
            acc[0][3] = fmaf(a.x, bb.w, acc[0][3]);
            acc[1][0] = fmaf(a.y, bb.x, acc[1][0]);
            acc[1][1] = fmaf(a.y, bb.y, acc[1][1]);
            acc[1][2] = fmaf(a.y, bb.z, acc[1][2]);
            acc[1][3] = fmaf(a.y, bb.w, acc[1][3]);
            acc[2][0] = fmaf(a.z, bb.x, acc[2][0]);
            acc[2][1] = fmaf(a.z, bb.y, acc[2][1]);
            acc[2][2] = fmaf(a.z, bb.z, acc[2][2]);
            acc[2][3] = fmaf(a.z, bb.w, acc[2][3]);
            acc[3][0] = fmaf(a.w, bb.x, acc[3][0]);
            acc[3][1] = fmaf(a.w, bb.y, acc[3][1]);
            acc[3][2] = fmaf(a.w, bb.z, acc[3][2]);
            acc[3][3] = fmaf(a.w, bb.w, acc[3][3]);
        }
        __syncthreads();
    }

    // Store
#pragma unroll
    for (int i = 0; i < 4; ++i) {
        int p = p0 + (ty << 2) + i;
        if (p >= P_) continue;
        float* orow = g_fastsim + ((size_t)(b * P_ + p)) * N_ + n0 + (tx << 2);
#pragma unroll
        for (int j = 0; j < 4; ++j) {
            int n = n0 + (tx << 2) + j;
            if (n < N_) orow[j] = acc[i][j];
        }
    }
}

// ---------------------------------------------------------------------------
// Kernel 2: per (b,p): radix-select top-512, rescore with posW, softmax-agg.
// ---------------------------------------------------------------------------
__device__ __forceinline__ unsigned fkey(float f) {
    unsigned u = __float_as_uint(f);
    return (u & 0x80000000u) ? ~u : (u | 0x80000000u);   // monotonic increasing
}

__global__ void __launch_bounds__(256) select_kernel(const float* __restrict__ neg,
                                                     const float* __restrict__ biasp,
                                                     const float* __restrict__ scalep,
                                                     float* __restrict__ out) {
    int row = blockIdx.x;        // b*P + p
    int b = row / P_;
    int tid = threadIdx.x;
    const float* sim = g_fastsim + (size_t)row * N_;

    __shared__ unsigned hist[2048];
    __shared__ int   sel[K_];
    __shared__ float sscore[K_];
    __shared__ int   ties[K_];
    __shared__ float spw[D_];
    __shared__ unsigned s_thresh, s_kr;
    __shared__ int s_cntgt, s_cnteq;
    __shared__ float red[256];

    if (tid < D_) spw[tid] = g_posW[row * D_ + tid];

    // ---- 3-pass radix select: find exact 512th-largest key ----
    unsigned prefix = 0, prefmask = 0, kr = K_;
    const int      shifts[3] = {21, 10, 0};
    const unsigned masks[3]  = {0x7FFu, 0x7FFu, 0x3FFu};

    for (int pass = 0; pass < 3; ++pass) {
        int sh = shifts[pass];
        unsigned mk = masks[pass];
        for (int i = tid; i < 2048; i += 256) hist[i] = 0;
        __syncthreads();
        for (int n = tid; n < N_; n += 256) {
            unsigned u = fkey(sim[n]);
            if ((u & prefmask) == prefix)
                atomicAdd(&hist[(u >> sh) & mk], 1u);
        }
        __syncthreads();
        if (tid == 0) {
            unsigned cum = 0;
            int bsel = 0;
            unsigned krl = kr;
            for (int bin = (int)mk; bin >= 0; --bin) {
                cum += hist[bin];
                if (cum >= krl) {
                    bsel = bin;
                    krl -= (cum - hist[bin]);   // remove strictly-greater count
                    break;
                }
            }
            s_thresh = prefix | ((unsigned)bsel << sh);
            s_kr = krl;
        }
        __syncthreads();
        prefix = s_thresh;
        kr = s_kr;
        prefmask |= mk << sh;
        __syncthreads();
    }
    unsigned uth = prefix;    // exact key of the 512th-largest element

    // ---- collect: all keys > uth, plus smallest-index ties == uth ----
    if (tid == 0) { s_cntgt = 0; s_cnteq = 0; }
    __syncthreads();
    for (int n = tid; n < N_; n += 256) {
        unsigned u = fkey(sim[n]);
        if (u > uth) {
            int q = atomicAdd(&s_cntgt, 1);
            sel[q] = n;
        } else if (u == uth) {
            int q = atomicAdd(&s_cnteq, 1);
            if (q < K_) ties[q] = n;
        }
    }
    __syncthreads();
    if (tid == 0) {
        int have = s_cntgt;
        int need = K_ - have;
        int te = min(s_cnteq, K_);
        for (int j = 0; j < need; ++j) {
            int bi = -1, bv = 0x7fffffff;
            for (int t = 0; t < te; ++t) {
                int v = ties[t];
                if (v >= 0 && v < bv) { bv = v; bi = t; }
            }
            if (bi >= 0) { ties[bi] = -1; sel[have + j] = bv; }
            else         { sel[have + j] = sel[0]; }  // unreachable safety
        }
    }
    __syncthreads();

    // ---- deterministic order: bitonic sort the 512 selected indices ----
    for (int k2 = 2; k2 <= K_; k2 <<= 1) {
        for (int j = k2 >> 1; j > 0; j >>= 1) {
            __syncthreads();
#pragma unroll
            for (int q = 0; q < 2; ++q) {
                int t = tid + q * 256;
                int ixj = t ^ j;
                if (ixj > t) {
                    int a = sel[t], c = sel[ixj];
                    bool asc = ((t & k2) == 0);
                    if (asc ? (a > c) : (a < c)) { sel[t] = c; sel[ixj] = a; }
                }
            }
        }
    }
    __syncthreads();

    // ---- rescore: score[s] = posW . neg[b, sel[s], :] + bias (warp per dot) ----
    int lane = tid & 31, wid = tid >> 5;
    float biasv = *biasp;
    for (int s = wid; s < K_; s += 8) {
        int idx = sel[s];
        const float* v = neg + ((size_t)b * N_ + idx) * D_;
        float sum = 0.f;
#pragma unroll
        for (int q = 0; q < 4; ++q)
            sum = fmaf(spw[lane + q * 32], v[lane + q * 32], sum);
#pragma unroll
        for (int o = 16; o; o >>= 1)
            sum += __shfl_xor_sync(0xffffffffu, sum, o);
        if (lane == 0) sscore[s] = sum + biasv;
    }
    __syncthreads();

    // ---- softmax aggregation: out = sum softmax(scale*s) * s ----
    float sc;
    {
        float x = *scalep;
        sc = (x > 20.f) ? x : log1pf(expf(x));   // softplus
    }
    float m = -INFINITY;
    for (int s = tid; s < K_; s += 256) m = fmaxf(m, sc * sscore[s]);
    red[tid] = m;
    __syncthreads();
    for (int o = 128; o; o >>= 1) {
        if (tid < o) red[tid] = fmaxf(red[tid], red[tid + o]);
        __syncthreads();
    }
    m = red[0];
    __syncthreads();

    float num = 0.f, den = 0.f;
    for (int s = tid; s < K_; s += 256) {
        float sv = sscore[s];
        float e = expf(sc * sv - m);
        num = fmaf(e, sv, num);
        den += e;
    }
    red[tid] = num;
    __syncthreads();
    for (int o = 128; o; o >>= 1) {
        if (tid < o) red[tid] += red[tid + o];
        __syncthreads();
    }
    num = red[0];
    __syncthreads();
    red[tid] = den;
    __syncthreads();
    for (int o = 128; o; o >>= 1) {
        if (tid < o) red[tid] += red[tid + o];
        __syncthreads();
    }
    den = red[0];

    if (tid == 0) out[row] = num / den;
}

// ---------------------------------------------------------------------------
extern "C" void kernel_launch(void* const* d_in, const int* in_sizes, int n_in,
                              void* d_out, int out_size) {
    const float* fea0  = (const float*)d_in[0];
    const float* neg   = (const float*)d_in[1];
    const float* W     = (const float*)d_in[2];
    const float* bias  = (const float*)d_in[3];
    const float* scale = (const float*)d_in[4];
    float* out = (float*)d_out;

    posw_kernel<<<B_ * P_, 128>>>(fea0, W);

    dim3 g1((N_ + TN - 1) / TN, (P_ + TP - 1) / TP, B_);
    fastsim_kernel<<<g1, 256>>>(fea0, neg);

    select_kernel<<<B_ * P_, 256>>>(neg, bias, scale, out);
}

// round 2
// speedup vs baseline: 1.8324x; 1.8324x over previous
#include <cuda_runtime.h>
#include <math.h>
#include <stdint.h>

#define B_ 8
#define P_ 100
#define N_ 50000
#define D_ 128
#define K_ 512

// Scratch (static device globals — no runtime allocation)
__device__ float g_fastsim[(size_t)B_ * P_ * N_];   // 160 MB
__device__ float g_posW[B_ * P_ * D_];              // 400 KB

// ---------------------------------------------------------------------------
// Kernel 0: posW[b,p,:] = pos[b,p,:] @ W
// ---------------------------------------------------------------------------
__global__ void posw_kernel(const float* __restrict__ pos, const float* __restrict__ W) {
    int row = blockIdx.x;
    int e = threadIdx.x;
    __shared__ float sp[D_];
    sp[e] = pos[(size_t)row * D_ + e];
    __syncthreads();
    float acc = 0.f;
#pragma unroll 8
    for (int d = 0; d < D_; ++d)
        acc = fmaf(sp[d], W[d * D_ + e], acc);
    g_posW[row * D_ + e] = acc;
}

// ---------------------------------------------------------------------------
// Kernel 1: fast_sim[b,p,n] = pos[b,p,:] . neg[b,n,:]
// TP=100 (all p, zero pad waste), TN=128, 640 threads (20x32), 5p x 4n microtile.
// A resident in smem for the whole CTA; B double-buffered via cp.async.
// ---------------------------------------------------------------------------
#define TNB 128
#define GT  640
#define AS_STRIDE 132     // 128 + 4 pad (float4-aligned)
#define BS_STRIDE 68      // 64 + 4 pad  (17 x 16B -> conflict-free f4 reads)
#define SMEM_GEMM_BYTES ((P_ * AS_STRIDE + 2 * TNB * BS_STRIDE) * 4)

__device__ __forceinline__ void cp16(uint32_t dst, const void* src) {
    asm volatile("cp.async.cg.shared.global [%0], [%1], 16;\n" :: "r"(dst), "l"(src));
}
__device__ __forceinline__ void cp_commit() {
    asm volatile("cp.async.commit_group;\n" ::: "memory");
}
__device__ __forceinline__ void cp_wait0() {
    asm volatile("cp.async.wait_group 0;\n" ::: "memory");
}

__global__ void __launch_bounds__(GT, 1) fastsim_kernel(const float* __restrict__ pos,
                                                        const float* __restrict__ neg) {
    extern __shared__ float smem[];
    float* As = smem;                       // [100][132]
    float* Bs = smem + P_ * AS_STRIDE;      // [2][128][68]

    int b  = blockIdx.y;
    int n0 = blockIdx.x * TNB;
    int tid = threadIdx.x;
    int tx = tid & 31;          // 0..31  (n groups)
    int ty = tid >> 5;          // 0..19  (p groups, 5 rows each)

    const float* Ab = pos + (size_t)b * P_ * D_;
    const float* Bb = neg + (size_t)b * N_ * D_;

    // --- issue async load of B chunk 0 (k = 0..63) ---
#pragma unroll
    for (int i = 0; i < 4; ++i) {
        int f = i * GT + tid;
        if (f < 2048) {
            int r = f >> 4;             // 0..127
            int c = (f & 15) << 2;      // 0..60
            int n = n0 + r;
            float* d = &Bs[(size_t)r * BS_STRIDE + c];
            if (n < N_) {
                cp16((uint32_t)__cvta_generic_to_shared(d), Bb + (size_t)n * D_ + c);
            } else {
                d[0] = 0.f; d[1] = 0.f; d[2] = 0.f; d[3] = 0.f;
            }
        }
    }
    cp_commit();

    // --- load full A (100x128) with plain loads ---
#pragma unroll
    for (int i = 0; i < 5; ++i) {
        int f = i * GT + tid;           // 0..3199
        int r = f >> 5;                 // 0..99
        int c = (f & 31) << 2;          // 0..124
        float4 v = *(const float4*)(Ab + (size_t)r * D_ + c);
        *(float4*)&As[(size_t)r * AS_STRIDE + c] = v;
    }

    float acc[5][4];
#pragma unroll
    for (int i = 0; i < 5; ++i)
#pragma unroll
        for (int j = 0; j < 4; ++j) acc[i][j] = 0.f;

#pragma unroll
    for (int kc = 0; kc < 2; ++kc) {
        cp_wait0();
        __syncthreads();

        if (kc == 0) {
            // issue async load of B chunk 1 (k = 64..127) while computing chunk 0
#pragma unroll
            for (int i = 0; i < 4; ++i) {
                int f = i * GT + tid;
                if (f < 2048) {
                    int r = f >> 4;
                    int c = (f & 15) << 2;
                    int n = n0 + r;
                    float* d = &Bs[(size_t)(TNB + r) * BS_STRIDE + c];
                    if (n < N_) {
                        cp16((uint32_t)__cvta_generic_to_shared(d), Bb + (size_t)n * D_ + 64 + c);
                    } else {
                        d[0] = 0.f; d[1] = 0.f; d[2] = 0.f; d[3] = 0.f;
                    }
                }
            }
            cp_commit();
        }

        const float* Bbuf = Bs + (size_t)kc * TNB * BS_STRIDE;
        int kbase = kc * 64;

#pragma unroll 4
        for (int k4 = 0; k4 < 16; ++k4) {
            float4 av[5];
#pragma unroll
            for (int i = 0; i < 5; ++i)
                av[i] = *(const float4*)&As[(size_t)(ty * 5 + i) * AS_STRIDE + kbase + k4 * 4];
#pragma unroll
            for (int j = 0; j < 4; ++j) {
                float4 bv = *(const float4*)&Bbuf[(size_t)(tx + j * 32) * BS_STRIDE + k4 * 4];
#pragma unroll
                for (int i = 0; i < 5; ++i) {
                    acc[i][j] = fmaf(av[i].x, bv.x, acc[i][j]);
                    acc[i][j] = fmaf(av[i].y, bv.y, acc[i][j]);
                    acc[i][j] = fmaf(av[i].z, bv.z, acc[i][j]);
                    acc[i][j] = fmaf(av[i].w, bv.w, acc[i][j]);
                }
            }
        }
    }

    // --- store ---
#pragma unroll
    for (int i = 0; i < 5; ++i) {
        int p = ty * 5 + i;             // always < 100
        float* orow = g_fastsim + ((size_t)(b * P_ + p)) * N_;
#pragma unroll
        for (int j = 0; j < 4; ++j) {
            int n = n0 + tx + j * 32;
            if (n < N_) orow[n] = acc[i][j];
        }
    }
}

// ---------------------------------------------------------------------------
// Kernel 2: per (b,p): sample-bounded exact top-512, rescore, softmax-agg.
// ---------------------------------------------------------------------------
#define SAMP 2048
#define CAP  3072

__device__ __forceinline__ unsigned fkey(float f) {
    unsigned u = __float_as_uint(f);
    return (u & 0x80000000u) ? ~u : (u | 0x80000000u);   // monotonic increasing
}

// cooperative scan of hist to find the bin containing the kr-th largest
__device__ void scan_bins(unsigned* hist, unsigned* csum, int nbins, int kr,
                          int sh, unsigned prefix,
                          unsigned* s_thresh, int* s_kr, int tid) {
    int chunks = nbins >> 3;
    if (tid < chunks) {
        unsigned s = 0;
#pragma unroll
        for (int i = 0; i < 8; ++i) s += hist[tid * 8 + i];
        csum[tid] = s;
    }
    __syncthreads();
    if (tid == 0) {
        unsigned cum = 0;
        int c = chunks - 1;
        for (; c > 0; --c) {
            if (cum + csum[c] >= (unsigned)kr) break;
            cum += csum[c];
        }
        int bin = c * 8 + 7;
        for (; bin > c * 8; --bin) {
            if (cum + hist[bin] >= (unsigned)kr) break;
            cum += hist[bin];
        }
        *s_thresh = prefix | ((unsigned)bin << sh);
        *s_kr = kr - (int)cum;
    }
    __syncthreads();
}

__global__ void __launch_bounds__(256) select_kernel(const float* __restrict__ neg,
                                                     const float* __restrict__ biasp,
                                                     const float* __restrict__ scalep,
                                                     float* __restrict__ out) {
    int row = blockIdx.x;
    int b = row / P_;
    int tid = threadIdx.x;
    const float* sim = g_fastsim + (size_t)row * N_;

    __shared__ unsigned hist[2048];
    __shared__ unsigned csum[256];
    __shared__ unsigned candk[CAP];
    __shared__ int      candi[CAP];
    __shared__ int      sel[K_];
    __shared__ float    sscore[K_];
    __shared__ int      ties[K_];
    __shared__ float    spw[D_];
    __shared__ float    red[256];
    __shared__ unsigned s_thresh;
    __shared__ int      s_kr, s_cnt, s_cntgt, s_cnteq;

    if (tid < D_) spw[tid] = g_posW[row * D_ + tid];

    const int      shifts[3] = {21, 10, 0};
    const unsigned masks[3]  = {0x7FFu, 0x7FFu, 0x3FFu};
    const int      nbinsv[3] = {2048, 2048, 1024};

    // ---- Step 1: exact 64th-largest key of the first-2048 sample -> lo ----
    unsigned skey[8];
#pragma unroll
    for (int q = 0; q < 2; ++q) {
        float4 v = *(const float4*)(sim + tid * 8 + q * 4);
        skey[q * 4 + 0] = fkey(v.x); skey[q * 4 + 1] = fkey(v.y);
        skey[q * 4 + 2] = fkey(v.z); skey[q * 4 + 3] = fkey(v.w);
    }
    unsigned prefix = 0, pmask = 0;
    int kr = 64;
    for (int pass = 0; pass < 3; ++pass) {
        int sh = shifts[pass]; unsigned mk = masks[pass];
#pragma unroll
        for (int i = 0; i < 8; ++i) hist[tid * 8 + i] = 0;
        __syncthreads();
#pragma unroll
        for (int i = 0; i < 8; ++i) {
            unsigned u = skey[i];
            if ((u & pmask) == prefix) atomicAdd(&hist[(u >> sh) & mk], 1u);
        }
        __syncthreads();
        scan_bins(hist, csum, nbinsv[pass], kr, sh, prefix, &s_thresh, &s_kr, tid);
        prefix = s_thresh; kr = s_kr; pmask |= mk << sh;
        __syncthreads();
    }
    unsigned lo = prefix;

    // ---- Step 2: collect candidates (key >= lo) from full row ----
    if (tid == 0) s_cnt = 0;
    __syncthreads();
    for (int f = tid; f < N_ / 4; f += 256) {
        float4 v = ((const float4*)sim)[f];
        unsigned u0 = fkey(v.x), u1 = fkey(v.y), u2 = fkey(v.z), u3 = fkey(v.w);
        if (u0 >= lo) { int q = atomicAdd(&s_cnt, 1); if (q < CAP) { candk[q] = u0; candi[q] = f * 4 + 0; } }
        if (u1 >= lo) { int q = atomicAdd(&s_cnt, 1); if (q < CAP) { candk[q] = u1; candi[q] = f * 4 + 1; } }
        if (u2 >= lo) { int q = atomicAdd(&s_cnt, 1); if (q < CAP) { candk[q] = u2; candi[q] = f * 4 + 2; } }
        if (u3 >= lo) { int q = atomicAdd(&s_cnt, 1); if (q < CAP) { candk[q] = u3; candi[q] = f * 4 + 3; } }
    }
    __syncthreads();
    int cnt = s_cnt;
    bool fallback = (cnt < K_) || (cnt > CAP);   // uniform across block

    // ---- Step 3: exact 512th-largest key -> uth (cand path or full fallback) ----
    prefix = 0; pmask = 0; kr = K_;
    for (int pass = 0; pass < 3; ++pass) {
        int sh = shifts[pass]; unsigned mk = masks[pass];
#pragma unroll
        for (int i = 0; i < 8; ++i) hist[tid * 8 + i] = 0;
        __syncthreads();
        if (!fallback) {
            for (int i = tid; i < cnt; i += 256) {
                unsigned u = candk[i];
                if ((u & pmask) == prefix) atomicAdd(&hist[(u >> sh) & mk], 1u);
            }
        } else {
            for (int n = tid; n < N_; n += 256) {
                unsigned u = fkey(sim[n]);
                if ((u & pmask) == prefix) atomicAdd(&hist[(u >> sh) & mk], 1u);
            }
        }
        __syncthreads();
        scan_bins(hist, csum, nbinsv[pass], kr, sh, prefix, &s_thresh, &s_kr, tid);
        prefix = s_thresh; kr = s_kr; pmask |= mk << sh;
        __syncthreads();
    }
    unsigned uth = prefix;

    // ---- Step 4: collect winners (> uth) and ties (== uth) ----
    if (tid == 0) { s_cntgt = 0; s_cnteq = 0; }
    __syncthreads();
    if (!fallback) {
        for (int i = tid; i < cnt; i += 256) {
            unsigned u = candk[i];
            if (u > uth) {
                int q = atomicAdd(&s_cntgt, 1);
                sel[q] = candi[i];
            } else if (u == uth) {
                int q = atomicAdd(&s_cnteq, 1);
                if (q < K_) ties[q] = candi[i];
            }
        }
    } else {
        for (int n = tid; n < N_; n += 256) {
            unsigned u = fkey(sim[n]);
            if (u > uth) {
                int q = atomicAdd(&s_cntgt, 1);
                sel[q] = n;
            } else if (u == uth) {
                int q = atomicAdd(&s_cnteq, 1);
                if (q < K_) ties[q] = n;
            }
        }
    }
    __syncthreads();
    if (tid == 0) {
        int have = s_cntgt;
        int need = K_ - have;              // usually 1
        int te = min(s_cnteq, K_);
        for (int j = 0; j < need; ++j) {
            int bi = -1, bv = 0x7fffffff;
            for (int t = 0; t < te; ++t) {
                int v = ties[t];
                if (v >= 0 && v < bv) { bv = v; bi = t; }
            }
            if (bi >= 0) { ties[bi] = -1; sel[have + j] = bv; }
            else         { sel[have + j] = sel[0]; }   // unreachable safety
        }
    }
    __syncthreads();

    // ---- Step 5: rescore selected 512 (warp per dot) ----
    int lane = tid & 31, wid = tid >> 5;
    float biasv = *biasp;
    for (int s = wid; s < K_; s += 8) {
        int idx = sel[s];
        const float* v = neg + ((size_t)b * N_ + idx) * D_;
        float sum = 0.f;
#pragma unroll
        for (int q = 0; q < 4; ++q)
            sum = fmaf(spw[lane + q * 32], v[lane + q * 32], sum);
#pragma unroll
        for (int o = 16; o; o >>= 1)
            sum += __shfl_xor_sync(0xffffffffu, sum, o);
        if (lane == 0) sscore[s] = sum + biasv;
    }
    __syncthreads();

    // ---- Step 6: softmax aggregation ----
    float sc;
    {
        float x = *scalep;
        sc = (x > 20.f) ? x : log1pf(expf(x));
    }
    float m = -INFINITY;
    for (int s = tid; s < K_; s += 256) m = fmaxf(m, sc * sscore[s]);
    red[tid] = m;
    __syncthreads();
    for (int o = 128; o; o >>= 1) {
        if (tid < o) red[tid] = fmaxf(red[tid], red[tid + o]);
        __syncthreads();
    }
    m = red[0];
    __syncthreads();

    float num = 0.f, den = 0.f;
    for (int s = tid; s < K_; s += 256) {
        float sv = sscore[s];
        float e = expf(sc * sv - m);
        num = fmaf(e, sv, num);
        den += e;
    }
    red[tid] = num;
    __syncthreads();
    for (int o = 128; o; o >>= 1) {
        if (tid < o) red[tid] += red[tid + o];
        __syncthreads();
    }
    num = red[0];
    __syncthreads();
    red[tid] = den;
    __syncthreads();
    for (int o = 128; o; o >>= 1) {
        if (tid < o) red[tid] += red[tid + o];
        __syncthreads();
    }
    den = red[0];

    if (tid == 0) out[row] = num / den;
}

// ---------------------------------------------------------------------------
extern "C" void kernel_launch(void* const* d_in, const int* in_sizes, int n_in,
                              void* d_out, int out_size) {
    const float* fea0  = (const float*)d_in[0];
    const float* neg   = (const float*)d_in[1];
    const float* W     = (const float*)d_in[2];
    const float* bias  = (const float*)d_in[3];
    const float* scale = (const float*)d_in[4];
    float* out = (float*)d_out;

    posw_kernel<<<B_ * P_, 128>>>(fea0, W);

    cudaFuncSetAttribute(fastsim_kernel,
                         cudaFuncAttributeMaxDynamicSharedMemorySize, SMEM_GEMM_BYTES);
    dim3 g1((N_ + TNB - 1) / TNB, B_);
    fastsim_kernel<<<g1, GT, SMEM_GEMM_BYTES>>>(fea0, neg);

    select_kernel<<<B_ * P_, 256>>>(neg, bias, scale, out);
}

// round 4
// speedup vs baseline: 2.3266x; 1.2697x over previous
#include <cuda_runtime.h>
#include <cuda_bf16.h>
#include <math.h>
#include <stdint.h>

#define B_ 8
#define P_ 100
#define N_ 50000
#define D_ 128
#define K_ 512

// Scratch (static device globals — no runtime allocation)
__device__ float g_fastsim[(size_t)B_ * P_ * N_];   // 160 MB
__device__ float g_posW[B_ * P_ * D_];              // 400 KB

// ---------------------------------------------------------------------------
// Kernel 0: posW[b,p,:] = pos[b,p,:] @ W
// ---------------------------------------------------------------------------
__global__ void posw_kernel(const float* __restrict__ pos, const float* __restrict__ W) {
    int row = blockIdx.x;
    int e = threadIdx.x;
    __shared__ float sp[D_];
    sp[e] = pos[(size_t)row * D_ + e];
    __syncthreads();
    float acc = 0.f;
#pragma unroll 8
    for (int d = 0; d < D_; ++d)
        acc = fmaf(sp[d], W[d * D_ + e], acc);
    g_posW[row * D_ + e] = acc;
}

// ---------------------------------------------------------------------------
// Kernel 1: fast_sim = pos @ neg^T, bf16x2-split on classic mma.sync (HMMA).
// CTA: 128(m=p rows, 100 real) x 128(n) tile, K=128. 8 warps, 64x32 per warp.
// smem tiles: A_hi, A_lo, B_hi, B_lo as [128 rows][136 bf16] (272B stride).
// ---------------------------------------------------------------------------
#define TNB 128
#define TSTR 136                       // bf16 elements per smem row (272 B)
#define TILE_BYTES (128 * TSTR * 2)    // 34816 B per tile
#define SMEM_TC_BYTES (4 * TILE_BYTES) // 139264 B

__device__ __forceinline__ uint32_t smem_u32(const void* p) {
    return (uint32_t)__cvta_generic_to_shared(p);
}

__device__ __forceinline__ void ldm_x4(uint32_t& r0, uint32_t& r1, uint32_t& r2, uint32_t& r3,
                                       uint32_t addr) {
    asm volatile("ldmatrix.sync.aligned.m8n8.x4.shared.b16 {%0,%1,%2,%3}, [%4];"
                 : "=r"(r0), "=r"(r1), "=r"(r2), "=r"(r3) : "r"(addr));
}
__device__ __forceinline__ void ldm_x2(uint32_t& r0, uint32_t& r1, uint32_t addr) {
    asm volatile("ldmatrix.sync.aligned.m8n8.x2.shared.b16 {%0,%1}, [%2];"
                 : "=r"(r0), "=r"(r1) : "r"(addr));
}
__device__ __forceinline__ void mma16816(float& c0, float& c1, float& c2, float& c3,
                                         uint32_t a0, uint32_t a1, uint32_t a2, uint32_t a3,
                                         uint32_t b0, uint32_t b1) {
    asm volatile("mma.sync.aligned.m16n8k16.row.col.f32.bf16.bf16.f32 "
                 "{%0,%1,%2,%3}, {%4,%5,%6,%7}, {%8,%9}, {%0,%1,%2,%3};"
                 : "+f"(c0), "+f"(c1), "+f"(c2), "+f"(c3)
                 : "r"(a0), "r"(a1), "r"(a2), "r"(a3), "r"(b0), "r"(b1));
}

__global__ void __launch_bounds__(256, 1) fastsim_tc_kernel(const float* __restrict__ pos,
                                                            const float* __restrict__ neg) {
    extern __shared__ __nv_bfloat16 smem[];
    __nv_bfloat16* Ah = smem;
    __nv_bfloat16* Al = smem + 128 * TSTR;
    __nv_bfloat16* Bh = smem + 2 * 128 * TSTR;
    __nv_bfloat16* Bl = smem + 3 * 128 * TSTR;

    int tid = threadIdx.x;
    int lane = tid & 31;
    int wid = tid >> 5;
    int b = blockIdx.y;
    int n0 = blockIdx.x * TNB;

    const float* Ab = pos + (size_t)b * P_ * D_;
    const float* Bb = neg + (size_t)b * N_ * D_;

    // ---- load + convert: A (128x128, rows>=100 zero), B (128x128, n>=N zero)
#pragma unroll
    for (int i = 0; i < 16; ++i) {
        int f = i * 256 + tid;          // 0..4095 float4 slots
        int r = f >> 5;                 // 0..127
        int c = (f & 31) << 2;          // 0..124

        // A
        float4 va = make_float4(0.f, 0.f, 0.f, 0.f);
        if (r < P_) va = *(const float4*)(Ab + (size_t)r * D_ + c);
        __nv_bfloat162 h0 = __float22bfloat162_rn(make_float2(va.x, va.y));
        __nv_bfloat162 h1 = __float22bfloat162_rn(make_float2(va.z, va.w));
        float2 hf0 = __bfloat1622float2(h0), hf1 = __bfloat1622float2(h1);
        __nv_bfloat162 l0 = __float22bfloat162_rn(make_float2(va.x - hf0.x, va.y - hf0.y));
        __nv_bfloat162 l1 = __float22bfloat162_rn(make_float2(va.z - hf1.x, va.w - hf1.y));
        *(uint2*)(Ah + r * TSTR + c) = make_uint2(*(uint32_t*)&h0, *(uint32_t*)&h1);
        *(uint2*)(Al + r * TSTR + c) = make_uint2(*(uint32_t*)&l0, *(uint32_t*)&l1);

        // B
        int n = n0 + r;
        float4 vb = make_float4(0.f, 0.f, 0.f, 0.f);
        if (n < N_) vb = *(const float4*)(Bb + (size_t)n * D_ + c);
        h0 = __float22bfloat162_rn(make_float2(vb.x, vb.y));
        h1 = __float22bfloat162_rn(make_float2(vb.z, vb.w));
        hf0 = __bfloat1622float2(h0); hf1 = __bfloat1622float2(h1);
        l0 = __float22bfloat162_rn(make_float2(vb.x - hf0.x, vb.y - hf0.y));
        l1 = __float22bfloat162_rn(make_float2(vb.z - hf1.x, vb.w - hf1.y));
        *(uint2*)(Bh + r * TSTR + c) = make_uint2(*(uint32_t*)&h0, *(uint32_t*)&h1);
        *(uint2*)(Bl + r * TSTR + c) = make_uint2(*(uint32_t*)&l0, *(uint32_t*)&l1);
    }
    __syncthreads();

    // ---- warp tiling: warp (wm, wn): m base wm*64, n base wn*32
    int wm = wid >> 2;       // 0..1
    int wn = wid & 3;        // 0..3
    int mbase = wm * 64;
    int nbase = wn * 32;

    float c[4][4][4];
#pragma unroll
    for (int i = 0; i < 4; ++i)
#pragma unroll
        for (int j = 0; j < 4; ++j)
#pragma unroll
            for (int q = 0; q < 4; ++q) c[i][j][q] = 0.f;

    const __nv_bfloat16* pA[3] = {Ah, Ah, Al};
    const __nv_bfloat16* pB[3] = {Bh, Bl, Bh};

#pragma unroll
    for (int pr = 0; pr < 3; ++pr) {
        uint32_t abase = smem_u32(pA[pr]);
        uint32_t bbase = smem_u32(pB[pr]);
        // lane-fixed components of ldmatrix addresses (bytes)
        uint32_t aoff = abase + (uint32_t)((lane & 15)) * (TSTR * 2) + (uint32_t)(lane >> 4) * 16;
        uint32_t boff = bbase + (uint32_t)((lane & 7)) * (TSTR * 2) + (uint32_t)((lane >> 3) & 1) * 16;

#pragma unroll
        for (int kc = 0; kc < 8; ++kc) {
            uint32_t kb = kc * 32;     // 16 bf16 = 32 bytes
            uint32_t a0[4], a1[4], a2[4], a3[4];
#pragma unroll
            for (int i = 0; i < 4; ++i)
                ldm_x4(a0[i], a1[i], a2[i], a3[i],
                       aoff + (uint32_t)(mbase + i * 16) * (TSTR * 2) + kb);
            uint32_t b0[4], b1[4];
#pragma unroll
            for (int j = 0; j < 4; ++j)
                ldm_x2(b0[j], b1[j],
                       boff + (uint32_t)(nbase + j * 8) * (TSTR * 2) + kb);
#pragma unroll
            for (int i = 0; i < 4; ++i)
#pragma unroll
                for (int j = 0; j < 4; ++j)
                    mma16816(c[i][j][0], c[i][j][1], c[i][j][2], c[i][j][3],
                             a0[i], a1[i], a2[i], a3[i], b0[j], b1[j]);
        }
    }

    // ---- epilogue: write fragments directly to g_fastsim
    int mrow0 = mbase + (lane >> 2);
    int ncol0 = n0 + nbase + (lane & 3) * 2;
#pragma unroll
    for (int i = 0; i < 4; ++i) {
        int m0 = mrow0 + i * 16;
        int m1 = m0 + 8;
#pragma unroll
        for (int j = 0; j < 4; ++j) {
            int nc = ncol0 + j * 8;
            if (nc + 1 < N_) {
                if (m0 < P_)
                    *(float2*)(g_fastsim + ((size_t)(b * P_ + m0)) * N_ + nc) =
                        make_float2(c[i][j][0], c[i][j][1]);
                if (m1 < P_)
                    *(float2*)(g_fastsim + ((size_t)(b * P_ + m1)) * N_ + nc) =
                        make_float2(c[i][j][2], c[i][j][3]);
            } else {
                // boundary tile: element-wise guard
                if (m0 < P_) {
                    float* row = g_fastsim + ((size_t)(b * P_ + m0)) * N_;
                    if (nc < N_)     row[nc]     = c[i][j][0];
                    if (nc + 1 < N_) row[nc + 1] = c[i][j][1];
                }
                if (m1 < P_) {
                    float* row = g_fastsim + ((size_t)(b * P_ + m1)) * N_;
                    if (nc < N_)     row[nc]     = c[i][j][2];
                    if (nc + 1 < N_) row[nc + 1] = c[i][j][3];
                }
            }
        }
    }
}

// ---------------------------------------------------------------------------
// Kernel 2: per (b,p): sample-bounded exact top-512, rescore, softmax-agg.
// ---------------------------------------------------------------------------
#define CAP  3072

__device__ __forceinline__ unsigned fkey(float f) {
    unsigned u = __float_as_uint(f);
    return (u & 0x80000000u) ? ~u : (u | 0x80000000u);   // monotonic increasing
}

__device__ void scan_bins(unsigned* hist, unsigned* csum, int nbins, int kr,
                          int sh, unsigned prefix,
                          unsigned* s_thresh, int* s_kr, int tid) {
    int chunks = nbins >> 3;
    if (tid < chunks) {
        unsigned s = 0;
#pragma unroll
        for (int i = 0; i < 8; ++i) s += hist[tid * 8 + i];
        csum[tid] = s;
    }
    __syncthreads();
    if (tid == 0) {
        unsigned cum = 0;
        int c = chunks - 1;
        for (; c > 0; --c) {
            if (cum + csum[c] >= (unsigned)kr) break;
            cum += csum[c];
        }
        int bin = c * 8 + 7;
        for (; bin > c * 8; --bin) {
            if (cum + hist[bin] >= (unsigned)kr) break;
            cum += hist[bin];
        }
        *s_thresh = prefix | ((unsigned)bin << sh);
        *s_kr = kr - (int)cum;
    }
    __syncthreads();
}

__global__ void __launch_bounds__(256) select_kernel(const float* __restrict__ neg,
                                                     const float* __restrict__ biasp,
                                                     const float* __restrict__ scalep,
                                                     float* __restrict__ out) {
    int row = blockIdx.x;
    int b = row / P_;
    int tid = threadIdx.x;
    const float* sim = g_fastsim + (size_t)row * N_;

    __shared__ unsigned hist[2048];
    __shared__ unsigned csum[256];
    __shared__ unsigned candk[CAP];
    __shared__ int      candi[CAP];
    __shared__ int      sel[K_];
    __shared__ float    sscore[K_];
    __shared__ int      ties[K_];
    __shared__ float    spw[D_];
    __shared__ float    red[256];
    __shared__ unsigned s_thresh;
    __shared__ int      s_kr, s_cnt, s_cntgt, s_cnteq;

    if (tid < D_) spw[tid] = g_posW[row * D_ + tid];

    const int      shifts[3] = {21, 10, 0};
    const unsigned masks[3]  = {0x7FFu, 0x7FFu, 0x3FFu};
    const int      nbinsv[3] = {2048, 2048, 1024};

    // ---- Step 1: exact 64th-largest key of first-2048 sample -> lo ----
    unsigned skey[8];
#pragma unroll
    for (int q = 0; q < 2; ++q) {
        float4 v = *(const float4*)(sim + tid * 8 + q * 4);
        skey[q * 4 + 0] = fkey(v.x); skey[q * 4 + 1] = fkey(v.y);
        skey[q * 4 + 2] = fkey(v.z); skey[q * 4 + 3] = fkey(v.w);
    }
    unsigned prefix = 0, pmask = 0;
    int kr = 64;
    for (int pass = 0; pass < 3; ++pass) {
        int sh = shifts[pass]; unsigned mk = masks[pass];
#pragma unroll
        for (int i = 0; i < 8; ++i) hist[tid * 8 + i] = 0;
        __syncthreads();
#pragma unroll
        for (int i = 0; i < 8; ++i) {
            unsigned u = skey[i];
            if ((u & pmask) == prefix) atomicAdd(&hist[(u >> sh) & mk], 1u);
        }
        __syncthreads();
        scan_bins(hist, csum, nbinsv[pass], kr, sh, prefix, &s_thresh, &s_kr, tid);
        prefix = s_thresh; kr = s_kr; pmask |= mk << sh;
        __syncthreads();
    }
    unsigned lo = prefix;

    // ---- Step 2: collect candidates (key >= lo) from full row ----
    if (tid == 0) s_cnt = 0;
    __syncthreads();
    for (int f = tid; f < N_ / 4; f += 256) {
        float4 v = ((const float4*)sim)[f];
        unsigned u0 = fkey(v.x), u1 = fkey(v.y), u2 = fkey(v.z), u3 = fkey(v.w);
        if (u0 >= lo) { int q = atomicAdd(&s_cnt, 1); if (q < CAP) { candk[q] = u0; candi[q] = f * 4 + 0; } }
        if (u1 >= lo) { int q = atomicAdd(&s_cnt, 1); if (q < CAP) { candk[q] = u1; candi[q] = f * 4 + 1; } }
        if (u2 >= lo) { int q = atomicAdd(&s_cnt, 1); if (q < CAP) { candk[q] = u2; candi[q] = f * 4 + 2; } }
        if (u3 >= lo) { int q = atomicAdd(&s_cnt, 1); if (q < CAP) { candk[q] = u3; candi[q] = f * 4 + 3; } }
    }
    __syncthreads();
    int cnt = s_cnt;
    bool fallback = (cnt < K_) || (cnt > CAP);

    // ---- Step 3: exact 512th-largest key -> uth ----
    prefix = 0; pmask = 0; kr = K_;
    for (int pass = 0; pass < 3; ++pass) {
        int sh = shifts[pass]; unsigned mk = masks[pass];
#pragma unroll
        for (int i = 0; i < 8; ++i) hist[tid * 8 + i] = 0;
        __syncthreads();
        if (!fallback) {
            for (int i = tid; i < cnt; i += 256) {
                unsigned u = candk[i];
                if ((u & pmask) == prefix) atomicAdd(&hist[(u >> sh) & mk], 1u);
            }
        } else {
            for (int n = tid; n < N_; n += 256) {
                unsigned u = fkey(sim[n]);
                if ((u & pmask) == prefix) atomicAdd(&hist[(u >> sh) & mk], 1u);
            }
        }
        __syncthreads();
        scan_bins(hist, csum, nbinsv[pass], kr, sh, prefix, &s_thresh, &s_kr, tid);
        prefix = s_thresh; kr = s_kr; pmask |= mk << sh;
        __syncthreads();
    }
    unsigned uth = prefix;

    // ---- Step 4: collect winners (> uth) and ties (== uth) ----
    if (tid == 0) { s_cntgt = 0; s_cnteq = 0; }
    __syncthreads();
    if (!fallback) {
        for (int i = tid; i < cnt; i += 256) {
            unsigned u = candk[i];
            if (u > uth) {
                int q = atomicAdd(&s_cntgt, 1);
                sel[q] = candi[i];
            } else if (u == uth) {
                int q = atomicAdd(&s_cnteq, 1);
                if (q < K_) ties[q] = candi[i];
            }
        }
    } else {
        for (int n = tid; n < N_; n += 256) {
            unsigned u = fkey(sim[n]);
            if (u > uth) {
                int q = atomicAdd(&s_cntgt, 1);
                sel[q] = n;
            } else if (u == uth) {
                int q = atomicAdd(&s_cnteq, 1);
                if (q < K_) ties[q] = n;
            }
        }
    }
    __syncthreads();
    if (tid == 0) {
        int have = s_cntgt;
        int need = K_ - have;
        int te = min(s_cnteq, K_);
        for (int j = 0; j < need; ++j) {
            int bi = -1, bv = 0x7fffffff;
            for (int t = 0; t < te; ++t) {
                int v = ties[t];
                if (v >= 0 && v < bv) { bv = v; bi = t; }
            }
            if (bi >= 0) { ties[bi] = -1; sel[have + j] = bv; }
            else         { sel[have + j] = sel[0]; }
        }
    }
    __syncthreads();

    // ---- Step 5: rescore selected 512 (warp per dot) ----
    int lane = tid & 31, wid = tid >> 5;
    float biasv = *biasp;
    for (int s = wid; s < K_; s += 8) {
        int idx = sel[s];
        const float* v = neg + ((size_t)b * N_ + idx) * D_;
        float sum = 0.f;
#pragma unroll
        for (int q = 0; q < 4; ++q)
            sum = fmaf(spw[lane + q * 32], v[lane + q * 32], sum);
#pragma unroll
        for (int o = 16; o; o >>= 1)
            sum += __shfl_xor_sync(0xffffffffu, sum, o);
        if (lane == 0) sscore[s] = sum + biasv;
    }
    __syncthreads();

    // ---- Step 6: softmax aggregation ----
    float sc;
    {
        float x = *scalep;
        sc = (x > 20.f) ? x : log1pf(expf(x));
    }
    float m = -INFINITY;
    for (int s = tid; s < K_; s += 256) m = fmaxf(m, sc * sscore[s]);
    red[tid] = m;
    __syncthreads();
    for (int o = 128; o; o >>= 1) {
        if (tid < o) red[tid] = fmaxf(red[tid], red[tid + o]);
        __syncthreads();
    }
    m = red[0];
    __syncthreads();

    float num = 0.f, den = 0.f;
    for (int s = tid; s < K_; s += 256) {
        float sv = sscore[s];
        float e = expf(sc * sv - m);
        num = fmaf(e, sv, num);
        den += e;
    }
    red[tid] = num;
    __syncthreads();
    for (int o = 128; o; o >>= 1) {
        if (tid < o) red[tid] += red[tid + o];
        __syncthreads();
    }
    num = red[0];
    __syncthreads();
    red[tid] = den;
    __syncthreads();
    for (int o = 128; o; o >>= 1) {
        if (tid < o) red[tid] += red[tid + o];
        __syncthreads();
    }
    den = red[0];

    if (tid == 0) out[row] = num / den;
}

// ---------------------------------------------------------------------------
extern "C" void kernel_launch(void* const* d_in, const int* in_sizes, int n_in,
                              void* d_out, int out_size) {
    const float* fea0  = (const float*)d_in[0];
    const float* neg   = (const float*)d_in[1];
    const float* W     = (const float*)d_in[2];
    const float* bias  = (const float*)d_in[3];
    const float* scale = (const float*)d_in[4];
    float* out = (float*)d_out;

    posw_kernel<<<B_ * P_, 128>>>(fea0, W);

    cudaFuncSetAttribute(fastsim_tc_kernel,
                         cudaFuncAttributeMaxDynamicSharedMemorySize, SMEM_TC_BYTES);
    dim3 g1((N_ + TNB - 1) / TNB, B_);
    fastsim_tc_kernel<<<g1, 256, SMEM_TC_BYTES>>>(fea0, neg);

    select_kernel<<<B_ * P_, 256>>>(neg, bias, scale, out);
}